// round 1
// baseline (speedup 1.0000x reference)
#include <cuda_runtime.h>
#include <cstdint>

// Problem constants
#define D        1024
#define NB       4
#define SEQ      2048
#define OUTSEQ   2049
#define NVOCAB   50257

// Chunked-scan parameters
#define CHUNKS   16          // independent chains
#define LCH      128         // outputs per chain
#define HW       64          // warm-up steps (0.64^65 ~ 3e-13 -> exact in fp32)
#define SSTEPS   (LCH + HW)  // 192 lock-step iterations
#define NCOL     (CHUNKS*NB) // 64 state columns

// GEMM tiling: out(1024 x 64) = M(1024x1024) * Y(1024x64) per step
#define NRB      16          // row blocks of 64 rows
#define NKS      8           // K splits of 128
#define RTILE    64
#define KTILE    128
#define GRID_MAIN (NRB*NKS)  // 128 CTAs  (<= 148 SMs -> co-resident)
#define THREADS  256
#define SPITCH   68          // padded smem row pitch (floats), 16B-aligned

// Device state
__device__ float    g_Y[2][NCOL][D];                 // double-buffered chain states
__device__ float    g_P[NRB][NKS][NCOL][RTILE];      // K-split partials [rb][ks][c][rlocal]
__device__ unsigned g_barCount;
__device__ volatile unsigned g_barGen;
__device__ int      g_ids64;                         // 1 if ids are int64, 0 if int32

// ---------------------------------------------------------------------------
// Grid-wide sense-reversing barrier (all CTAs resident in one wave)
// ---------------------------------------------------------------------------
__device__ __forceinline__ void grid_barrier() {
    __syncthreads();
    if (threadIdx.x == 0) {
        unsigned gen = g_barGen;
        __threadfence();
        unsigned arrived = atomicAdd(&g_barCount, 1u);
        if (arrived == GRID_MAIN - 1) {
            atomicExch(&g_barCount, 0u);
            __threadfence();
            g_barGen = gen + 1u;
        } else {
            while (g_barGen == gen) { __nanosleep(64); }
        }
        __threadfence();
    }
    __syncthreads();
}

// ---------------------------------------------------------------------------
// Kernel 0: detect ids dtype (int64 vs int32). For int64 (LE), every odd
// 32-bit word is 0 (ids in [0, 50257)). For int32, the odd words are real ids
// (prob of all 4096 being zero ~ 0). Single block.
// ---------------------------------------------------------------------------
__global__ void detect_kernel(const unsigned* ids32) {
    __shared__ unsigned red[256];
    unsigned acc = 0;
    for (int i = threadIdx.x; i < NB * SEQ; i += 256)
        acc |= ids32[2 * i + 1];
    red[threadIdx.x] = acc;
    __syncthreads();
    for (int off = 128; off > 0; off >>= 1) {
        if (threadIdx.x < off) red[threadIdx.x] |= red[threadIdx.x + off];
        __syncthreads();
    }
    if (threadIdx.x == 0) g_ids64 = (red[0] == 0u) ? 1 : 0;
}

// ---------------------------------------------------------------------------
// Kernel 1: init states, barrier vars, and the t=0 output rows (y0 = emb[0])
// ---------------------------------------------------------------------------
__global__ void init_kernel(const float* __restrict__ emb, float* __restrict__ out) {
    int i = blockIdx.x * blockDim.x + threadIdx.x;
    if (i == 0) { g_barCount = 0u; g_barGen = 0u; }
    if (i < NCOL * D) {
        int c = i >> 10;
        int k = i & (D - 1);
        // chain 0 (cols 0..3) starts exactly at y0 = emb[0]; others warm up from 0
        g_Y[0][c][k] = (c < NB) ? emb[k] : 0.0f;
    }
    if (i < NB * D) {
        int b = i >> 10;
        int r = i & (D - 1);
        out[(size_t)b * OUTSEQ * D + r] = emb[r];   // out[b][0][:] = emb[0]
    }
}

// ---------------------------------------------------------------------------
// Main persistent kernel: 192 lock-step GEMM+update iterations
// ---------------------------------------------------------------------------
__global__ void __launch_bounds__(THREADS, 1)
scan_kernel(const int* __restrict__ ids32,
            const float* __restrict__ emb,
            const float* __restrict__ Mw,
            float* __restrict__ out) {
    extern __shared__ float sm[];
    float* Ms = sm;                   // [KTILE][SPITCH] transposed M slice (persistent)
    float* Ys = sm + KTILE * SPITCH;  // [KTILE][SPITCH] transposed Y slice (per step)

    const int tid = threadIdx.x;
    const int rb  = blockIdx.x >> 3;        // row block  (16)
    const int ks  = blockIdx.x & (NKS - 1); // K split    (8)
    const int r0  = rb * RTILE;
    const int k0  = ks * KTILE;
    const int ids64 = g_ids64;

    // Load this CTA's M slice ONCE, transposed: Ms[k][r] = Mw[r0+r][k0+k]
    for (int i = tid; i < RTILE * KTILE; i += THREADS) {
        int r = i >> 7;            // / KTILE
        int k = i & (KTILE - 1);
        Ms[k * SPITCH + r] = Mw[(size_t)(r0 + r) * D + k0 + k];
    }

    const int tr = tid & 15;   // 16 row-thread groups  -> rows 4*tr..
    const int tc = tid >> 4;   // 16 col-thread groups  -> cols 4*tc..
    const float* msp = Ms + tr * 4;
    const float* ysp = Ys + tc * 4;

    int p = 0;
    for (int s = 0; s < SSTEPS; ++s) {
        __syncthreads();
        // Stage Y slice (transposed): Ys[k][c] = g_Y[p][c][k0+k]
        for (int i = tid; i < NCOL * (KTILE / 4); i += THREADS) {
            int c  = i >> 5;           // / 32
            int kq = (i & 31) << 2;
            float4 v = *reinterpret_cast<const float4*>(&g_Y[p][c][k0 + kq]);
            Ys[(kq + 0) * SPITCH + c] = v.x;
            Ys[(kq + 1) * SPITCH + c] = v.y;
            Ys[(kq + 2) * SPITCH + c] = v.z;
            Ys[(kq + 3) * SPITCH + c] = v.w;
        }
        __syncthreads();

        // 4x4 register-tile GEMM over this CTA's K range
        float acc[4][4];
        #pragma unroll
        for (int i = 0; i < 4; ++i)
            #pragma unroll
            for (int j = 0; j < 4; ++j) acc[i][j] = 0.0f;

        #pragma unroll 8
        for (int k = 0; k < KTILE; ++k) {
            float4 a = *reinterpret_cast<const float4*>(msp + k * SPITCH);
            float4 b = *reinterpret_cast<const float4*>(ysp + k * SPITCH);
            acc[0][0] += a.x * b.x; acc[0][1] += a.x * b.y; acc[0][2] += a.x * b.z; acc[0][3] += a.x * b.w;
            acc[1][0] += a.y * b.x; acc[1][1] += a.y * b.y; acc[1][2] += a.y * b.z; acc[1][3] += a.y * b.w;
            acc[2][0] += a.z * b.x; acc[2][1] += a.z * b.y; acc[2][2] += a.z * b.z; acc[2][3] += a.z * b.w;
            acc[3][0] += a.w * b.x; acc[3][1] += a.w * b.y; acc[3][2] += a.w * b.z; acc[3][3] += a.w * b.w;
        }

        // Write partials: g_P[rb][ks][c][rlocal], coalesced float4 over rows
        float* pb = &g_P[rb][ks][0][0];
        #pragma unroll
        for (int ci = 0; ci < 4; ++ci) {
            float4 v = make_float4(acc[0][ci], acc[1][ci], acc[2][ci], acc[3][ci]);
            *reinterpret_cast<float4*>(&pb[(tc * 4 + ci) * RTILE + tr * 4]) = v;
        }
        __threadfence();
        grid_barrier();

        // Phase B: reduce K-splits, add embedding, advance state, write output
        #pragma unroll
        for (int it = 0; it < 2; ++it) {
            int o = blockIdx.x * 512 + it * 256 + tid; // 0..65535, r-inner
            int c = o >> 10;
            int r = o & (D - 1);
            int j = c >> 2;
            int b = c & 3;
            int t = j * LCH + s - (HW - 1);   // global time of this chain at step s
            float v;
            if (t < 1) {
                v = g_Y[p][c][r];             // chain 0 pre-start: carry y0 forward
            } else {
                int rb2 = r >> 6, rl = r & 63;
                float sum = 0.0f;
                #pragma unroll
                for (int q = 0; q < NKS; ++q) sum += g_P[rb2][q][c][rl];
                int idx = b * SEQ + (t - 1);
                long long id = ids64 ? (long long)ids32[2 * idx] : (long long)ids32[idx];
                v = sum + emb[(size_t)id * D + r];
            }
            g_Y[p ^ 1][c][r] = v;
            if (s >= HW)
                out[((size_t)b * OUTSEQ + t) * D + r] = v;
        }
        __threadfence();
        grid_barrier();
        p ^= 1;
    }
}

// ---------------------------------------------------------------------------
extern "C" void kernel_launch(void* const* d_in, const int* in_sizes, int n_in,
                              void* d_out, int out_size) {
    const int*   ids = (const int*)d_in[0];   // int32 or int64 (auto-detected)
    const float* emb = (const float*)d_in[1]; // [50257][1024] fp32
    const float* Mw  = (const float*)d_in[2]; // [1024][1024] fp32
    float*       out = (float*)d_out;         // [4][2049][1024] fp32

    (void)in_sizes; (void)n_in; (void)out_size;

    const int smem = 2 * KTILE * SPITCH * (int)sizeof(float); // 69632 B
    cudaFuncSetAttribute(scan_kernel, cudaFuncAttributeMaxDynamicSharedMemorySize, smem);

    detect_kernel<<<1, 256>>>((const unsigned*)d_in[0]);
    init_kernel<<<(NCOL * D) / THREADS, THREADS>>>(emb, out);
    scan_kernel<<<GRID_MAIN, THREADS, smem>>>(ids, emb, Mw, out);
}

// round 2
// speedup vs baseline: 1.1703x; 1.1703x over previous
#include <cuda_runtime.h>
#include <cstdint>

// Problem constants
#define D        1024
#define NB       4
#define SEQ      2048
#define OUTSEQ   2049

// Chunked-scan parameters
#define CHUNKS   16
#define LCH      128
#define HW       64
#define SSTEPS   (LCH + HW)   // 192
#define NCOL     (CHUNKS*NB)  // 64 state columns

// GEMM tiling: Ynew(1024 x 64) = M(1024x1024) * Y(1024x64) per step
#define NRB      8            // row blocks of RT=128
#define RT       128
#define NKS      16           // K splits of KT=64
#define KT       64
#define GRID_MAIN (NRB*NKS)   // 128 CTAs
#define THREADS  256

// Device state
__device__ float    g_Y[2][NCOL][D];
__device__ float    g_P[NRB][NKS][NCOL][RT];   // K-split partials
__device__ unsigned g_barCount;
__device__ volatile unsigned g_barGen;
__device__ int      g_ids64;

// packed fp32x2 FMA (Blackwell: 2x fp32 rate, PTX-only)
__device__ __forceinline__ void fma2(float2& d, const float2& a, const float2& b) {
    asm("fma.rn.f32x2 %0, %1, %2, %0;"
        : "+l"(*reinterpret_cast<unsigned long long*>(&d))
        : "l"(*reinterpret_cast<const unsigned long long*>(&a)),
          "l"(*reinterpret_cast<const unsigned long long*>(&b)));
}

// ---------------------------------------------------------------------------
__device__ __forceinline__ void grid_barrier() {
    __syncthreads();
    if (threadIdx.x == 0) {
        unsigned gen = g_barGen;
        __threadfence();
        unsigned arrived = atomicAdd(&g_barCount, 1u);
        if (arrived == GRID_MAIN - 1) {
            atomicExch(&g_barCount, 0u);
            __threadfence();
            g_barGen = gen + 1u;
        } else {
            while (g_barGen == gen) { __nanosleep(32); }
        }
        __threadfence();
    }
    __syncthreads();
}

// ---------------------------------------------------------------------------
__global__ void detect_kernel(const unsigned* ids32) {
    __shared__ unsigned red[256];
    unsigned acc = 0;
    for (int i = threadIdx.x; i < NB * SEQ; i += 256)
        acc |= ids32[2 * i + 1];
    red[threadIdx.x] = acc;
    __syncthreads();
    for (int off = 128; off > 0; off >>= 1) {
        if (threadIdx.x < off) red[threadIdx.x] |= red[threadIdx.x + off];
        __syncthreads();
    }
    if (threadIdx.x == 0) g_ids64 = (red[0] == 0u) ? 1 : 0;
}

// ---------------------------------------------------------------------------
__global__ void init_kernel(const float* __restrict__ emb, float* __restrict__ out) {
    int i = blockIdx.x * blockDim.x + threadIdx.x;
    if (i == 0) { g_barCount = 0u; g_barGen = 0u; }
    if (i < NCOL * D) {
        int c = i >> 10;
        int k = i & (D - 1);
        g_Y[0][c][k] = (c < NB) ? emb[k] : 0.0f;
    }
    if (i < NB * D) {
        int b = i >> 10;
        int r = i & (D - 1);
        out[(size_t)b * OUTSEQ * D + r] = emb[r];
    }
}

// ---------------------------------------------------------------------------
// Main persistent kernel
// smem: Ms[128 rows][64 k] swizzled (32KB, persistent)
//       Ys[64 cols][64 k] swizzled (16KB, restaged per step)
// K-pairs packed into f32x2 lanes; XOR swizzle at 8B granularity:
//   Ms element (r,k): float2 slot = r*32 + ((k>>1) ^ (r>>3))
//   Ys element (c,k): float2 slot = c*32 + ((k>>1) ^ (c>>2))
// ---------------------------------------------------------------------------
__global__ void __launch_bounds__(THREADS, 1)
scan_kernel(const int* __restrict__ ids32,
            const float* __restrict__ emb,
            const float* __restrict__ Mw,
            float* __restrict__ out) {
    extern __shared__ float sm[];
    float2* Ms2 = reinterpret_cast<float2*>(sm);             // 128*32 float2
    float2* Ys2 = reinterpret_cast<float2*>(sm + RT * KT);   // 64*32 float2

    const int tid = threadIdx.x;
    const int rb  = blockIdx.x >> 4;         // 8 row blocks
    const int ks  = blockIdx.x & (NKS - 1);  // 16 K splits
    const int r0c = rb * RT;
    const int k0  = ks * KT;
    const int ids64 = g_ids64;

    // Load M slice once, swizzled (gmem-coalesced reads)
    for (int i = tid; i < RT * KT / 2; i += THREADS) {
        int r  = i >> 5;             // row
        int kp = i & 31;             // k pair
        float2 v;
        v.x = Mw[(size_t)(r0c + r) * D + k0 + 2 * kp];
        v.y = Mw[(size_t)(r0c + r) * D + k0 + 2 * kp + 1];
        Ms2[r * 32 + (kp ^ ((r >> 3) & 15))] = v;
    }

    const int rowg = tid & 15;    // 16 row groups of 8 rows
    const int colg = tid >> 4;    // 16 col groups of 4 cols
    const int r0 = rowg * 8;
    const int c0 = colg * 4;
    const float2* __restrict__ msp = Ms2 + r0 * 32;
    const float2* __restrict__ ysp = Ys2 + c0 * 32;

    int p = 0;
    for (int s = 0; s < SSTEPS; ++s) {
        __syncthreads();
        // Stage Y slice, swizzled: 64 cols x 64 k
        for (int i = tid; i < NCOL * (KT / 4); i += THREADS) {  // 1024 iters, 4/thread
            int c  = i >> 4;
            int kq = (i & 15) << 2;            // k quad
            float4 v = *reinterpret_cast<const float4*>(&g_Y[p][c][k0 + kq]);
            int sb = (c >> 2) & 15;
            int kp0 = kq >> 1;
            Ys2[c * 32 + (kp0 ^ sb)]       = make_float2(v.x, v.y);
            Ys2[c * 32 + ((kp0 + 1) ^ sb)] = make_float2(v.z, v.w);
        }
        __syncthreads();

        // 8x4 register tile, K-pair-packed f32x2 FMA
        float2 acc[8][4];
        #pragma unroll
        for (int i = 0; i < 8; ++i)
            #pragma unroll
            for (int j = 0; j < 4; ++j) acc[i][j] = make_float2(0.f, 0.f);

        #pragma unroll 4
        for (int kp = 0; kp < 32; ++kp) {
            int sa = kp ^ rowg;
            int sb = kp ^ colg;
            float2 a[8], b[4];
            #pragma unroll
            for (int i = 0; i < 8; ++i) a[i] = msp[i * 32 + sa];
            #pragma unroll
            for (int j = 0; j < 4; ++j) b[j] = ysp[j * 32 + sb];
            #pragma unroll
            for (int i = 0; i < 8; ++i)
                #pragma unroll
                for (int j = 0; j < 4; ++j) fma2(acc[i][j], a[i], b[j]);
        }

        // Horizontal add + write partials: g_P[rb][ks][c][r], r contiguous
        {
            float* pb = &g_P[rb][ks][0][0];
            #pragma unroll
            for (int j = 0; j < 4; ++j) {
                float4 v0 = make_float4(acc[0][j].x + acc[0][j].y, acc[1][j].x + acc[1][j].y,
                                        acc[2][j].x + acc[2][j].y, acc[3][j].x + acc[3][j].y);
                float4 v1 = make_float4(acc[4][j].x + acc[4][j].y, acc[5][j].x + acc[5][j].y,
                                        acc[6][j].x + acc[6][j].y, acc[7][j].x + acc[7][j].y);
                *reinterpret_cast<float4*>(&pb[(c0 + j) * RT + r0])     = v0;
                *reinterpret_cast<float4*>(&pb[(c0 + j) * RT + r0 + 4]) = v1;
            }
        }
        __threadfence();
        grid_barrier();

        // Phase B: reduce 16 K-splits, add embedding, advance, write output
        {
            int o  = blockIdx.x * THREADS + tid;   // 0..32767 float2 slots
            int c  = o >> 9;                       // 512 pairs per column
            int r  = (o & 511) << 1;
            int j  = c >> 2;
            int b  = c & 3;
            int t  = j * LCH + s - (HW - 1);
            float2 v;
            if (t < 1) {
                v = *reinterpret_cast<const float2*>(&g_Y[p][c][r]);
            } else {
                int rb2 = r >> 7, rl = r & 127;
                float sx = 0.f, sy = 0.f;
                #pragma unroll
                for (int q = 0; q < NKS; ++q) {
                    float2 pv = *reinterpret_cast<const float2*>(&g_P[rb2][q][c][rl]);
                    sx += pv.x; sy += pv.y;
                }
                int idx = b * SEQ + (t - 1);
                long long id = ids64 ? (long long)ids32[2 * idx] : (long long)ids32[idx];
                float2 e = *reinterpret_cast<const float2*>(&emb[(size_t)id * D + r]);
                v = make_float2(sx + e.x, sy + e.y);
            }
            *reinterpret_cast<float2*>(&g_Y[p ^ 1][c][r]) = v;
            if (s >= HW)
                *reinterpret_cast<float2*>(&out[((size_t)b * OUTSEQ + t) * D + r]) = v;
        }
        __threadfence();
        grid_barrier();
        p ^= 1;
    }
}

// ---------------------------------------------------------------------------
extern "C" void kernel_launch(void* const* d_in, const int* in_sizes, int n_in,
                              void* d_out, int out_size) {
    const int*   ids = (const int*)d_in[0];
    const float* emb = (const float*)d_in[1];
    const float* Mw  = (const float*)d_in[2];
    float*       out = (float*)d_out;

    (void)in_sizes; (void)n_in; (void)out_size;

    const int smem = (RT * KT + NCOL * KT) * (int)sizeof(float);  // 48KB
    cudaFuncSetAttribute(scan_kernel, cudaFuncAttributeMaxDynamicSharedMemorySize, smem);

    detect_kernel<<<1, 256>>>((const unsigned*)d_in[0]);
    init_kernel<<<(NCOL * D) / THREADS, THREADS>>>(emb, out);
    scan_kernel<<<GRID_MAIN, THREADS, smem>>>(ids, emb, Mw, out);
}

// round 4
// speedup vs baseline: 1.8224x; 1.5572x over previous
#include <cuda_runtime.h>
#include <cstdint>

// Problem constants
#define D        1024
#define NB       4
#define SEQ      2048
#define OUTSEQ   2049

// Chunked-scan parameters
#define CHUNKS   32
#define LCH      64           // SEQ / CHUNKS
#define HW       48           // warm-up; 0.64^48 ~ 2e-10
#define SSTEPS   (LCH + HW)   // 112
#define NCOL     (CHUNKS*NB)  // 128 state columns

// GEMM tiling: Ynew(1024 x 128) = M(1024x1024) * Y(1024x128) per step
#define NRB      8            // row blocks of RT=128
#define RT       128
#define NKS      16           // K splits of KT=64
#define KT       64
#define GRID_MAIN (NRB*NKS)   // 128 CTAs
#define THREADS  256

// Device state
__device__ float    g_Y[2][NCOL][D];               // double-buffered chain states
__device__ float    g_P[NRB][NKS][NCOL][RT];       // K-split partials (8MB)
__device__ unsigned g_barCount;
__device__ unsigned g_barGen;
__device__ int      g_ids64;

// packed fp32x2 FMA (Blackwell, PTX-only)
__device__ __forceinline__ void fma2(float2& d, const float2& a, const float2& b) {
    asm("fma.rn.f32x2 %0, %1, %2, %0;"
        : "+l"(*reinterpret_cast<unsigned long long*>(&d))
        : "l"(*reinterpret_cast<const unsigned long long*>(&a)),
          "l"(*reinterpret_cast<const unsigned long long*>(&b)));
}

// gpu-scope release/acquire primitives (no membar, no L1 flush)
__device__ __forceinline__ unsigned atom_add_release(unsigned* p, unsigned v) {
    unsigned old;
    asm volatile("atom.release.gpu.global.add.u32 %0, [%1], %2;"
                 : "=r"(old) : "l"(p), "r"(v) : "memory");
    return old;
}
__device__ __forceinline__ unsigned ld_acquire(unsigned* p) {
    unsigned v;
    asm volatile("ld.acquire.gpu.global.u32 %0, [%1];" : "=r"(v) : "l"(p) : "memory");
    return v;
}
__device__ __forceinline__ void st_release(unsigned* p, unsigned v) {
    asm volatile("st.release.gpu.global.u32 [%0], %1;" :: "l"(p), "r"(v) : "memory");
}
__device__ __forceinline__ void st_relaxed(unsigned* p, unsigned v) {
    asm volatile("st.relaxed.gpu.global.u32 [%0], %1;" :: "l"(p), "r"(v) : "memory");
}

// Grid barrier: all prior STG.cg from this CTA are ordered by bar.sync (intra-CTA)
// + release-atomic arrival; waiters synchronize via ld.acquire spin. Cross-CTA
// data uses .cg (L2) exclusively, so no L1 coherence hazard.
__device__ __forceinline__ void grid_barrier(unsigned gen) {
    __syncthreads();
    if (threadIdx.x == 0) {
        unsigned arrived = atom_add_release(&g_barCount, 1u);
        if (arrived == GRID_MAIN - 1) {
            st_relaxed(&g_barCount, 0u);
            st_release(&g_barGen, gen);
        } else {
            while (ld_acquire(&g_barGen) < gen) { __nanosleep(32); }
        }
    }
    __syncthreads();
}

// ---------------------------------------------------------------------------
__global__ void detect_kernel(const unsigned* ids32) {
    __shared__ unsigned red[256];
    unsigned acc = 0;
    for (int i = threadIdx.x; i < NB * SEQ; i += 256)
        acc |= ids32[2 * i + 1];
    red[threadIdx.x] = acc;
    __syncthreads();
    for (int off = 128; off > 0; off >>= 1) {
        if (threadIdx.x < off) red[threadIdx.x] |= red[threadIdx.x + off];
        __syncthreads();
    }
    if (threadIdx.x == 0) g_ids64 = (red[0] == 0u) ? 1 : 0;
}

// ---------------------------------------------------------------------------
__global__ void init_kernel(const float* __restrict__ emb, float* __restrict__ out) {
    int i = blockIdx.x * blockDim.x + threadIdx.x;
    if (i == 0) { g_barCount = 0u; g_barGen = 0u; }
    if (i < NCOL * D) {
        int c = i >> 10;
        int k = i & (D - 1);
        g_Y[0][c][k] = (c < NB) ? emb[k] : 0.0f;   // chain 0 starts at y0=emb[0]
    }
    if (i < NB * D) {
        int b = i >> 10;
        int r = i & (D - 1);
        out[(size_t)b * OUTSEQ * D + r] = emb[r];
    }
}

// ---------------------------------------------------------------------------
// Main persistent kernel.
// smem (float2 view): Ms2[128 r][32 kp] swizzled, persistent (32KB)
//                     Ys2[128 c][32 kp] swizzled, restaged per step (32KB)
// Swizzle: slot = row*32 + (kp ^ (row>>3))  -> conflict-free 8x8-tile LDS.64
// ---------------------------------------------------------------------------
__global__ void __launch_bounds__(THREADS, 1)
scan_kernel(const int* __restrict__ ids32,
            const float* __restrict__ emb,
            const float* __restrict__ Mw,
            float* __restrict__ out) {
    extern __shared__ float sm[];
    float2* Ms2 = reinterpret_cast<float2*>(sm);             // 128*32 float2
    float2* Ys2 = reinterpret_cast<float2*>(sm + RT * KT);   // 128*32 float2

    const int tid = threadIdx.x;
    const int rb  = blockIdx.x >> 4;          // 8 row blocks
    const int ks  = blockIdx.x & (NKS - 1);   // 16 K splits
    const int r0c = rb * RT;
    const int k0  = ks * KT;
    const int ids64 = g_ids64;

    // Load M slice once, swizzled
    for (int i = tid; i < RT * KT / 2; i += THREADS) {
        int r  = i >> 5;
        int kp = i & 31;
        float2 v = *reinterpret_cast<const float2*>(&Mw[(size_t)(r0c + r) * D + k0 + 2 * kp]);
        Ms2[r * 32 + (kp ^ (r >> 3))] = v;
    }

    const int rowg = tid & 15;     // 16 row groups of 8 rows
    const int colg = tid >> 4;     // 16 col groups of 8 cols
    const int r0 = rowg * 8;
    const int c0 = colg * 8;
    const float2* __restrict__ msp = Ms2 + r0 * 32;
    const float2* __restrict__ ysp = Ys2 + c0 * 32;

    int p = 0;
    unsigned gen = 0;
    for (int s = 0; s < SSTEPS; ++s) {
        // Stage Y slice (L2-scoped loads), swizzled: 128 cols x 64 k
        for (int i = tid; i < NCOL * (KT / 4); i += THREADS) {   // 2048 -> 8/thread
            int c  = i >> 4;
            int kq = (i & 15) << 2;
            float4 v = __ldcg(reinterpret_cast<const float4*>(&g_Y[p][c][k0 + kq]));
            int sw  = c >> 3;
            int kp0 = kq >> 1;
            Ys2[c * 32 + (kp0 ^ sw)]       = make_float2(v.x, v.y);
            Ys2[c * 32 + ((kp0 + 1) ^ sw)] = make_float2(v.z, v.w);
        }
        __syncthreads();

        // 8x8 register tile, K-pair-packed f32x2 FMA (crossbar-balanced)
        float2 acc[8][8];
        #pragma unroll
        for (int i = 0; i < 8; ++i)
            #pragma unroll
            for (int j = 0; j < 8; ++j) acc[i][j] = make_float2(0.f, 0.f);

        #pragma unroll 4
        for (int kp = 0; kp < 32; ++kp) {
            int sa = kp ^ rowg;
            int sb = kp ^ colg;
            float2 a[8], b[8];
            #pragma unroll
            for (int i = 0; i < 8; ++i) a[i] = msp[i * 32 + sa];
            #pragma unroll
            for (int j = 0; j < 8; ++j) b[j] = ysp[j * 32 + sb];
            #pragma unroll
            for (int i = 0; i < 8; ++i)
                #pragma unroll
                for (int j = 0; j < 8; ++j) fma2(acc[i][j], a[i], b[j]);
        }

        // Horizontal add + write partials via L2 (.cg): g_P[rb][ks][c][r]
        {
            float* pb = &g_P[rb][ks][0][0];
            #pragma unroll
            for (int j = 0; j < 8; ++j) {
                float4 v0 = make_float4(acc[0][j].x + acc[0][j].y, acc[1][j].x + acc[1][j].y,
                                        acc[2][j].x + acc[2][j].y, acc[3][j].x + acc[3][j].y);
                float4 v1 = make_float4(acc[4][j].x + acc[4][j].y, acc[5][j].x + acc[5][j].y,
                                        acc[6][j].x + acc[6][j].y, acc[7][j].x + acc[7][j].y);
                __stcg(reinterpret_cast<float4*>(&pb[(c0 + j) * RT + r0]),     v0);
                __stcg(reinterpret_cast<float4*>(&pb[(c0 + j) * RT + r0 + 4]), v1);
            }
        }
        grid_barrier(++gen);

        // Phase B: reduce 16 K-splits, add embedding, advance state, write out
        #pragma unroll
        for (int it = 0; it < 2; ++it) {
            int o = blockIdx.x * 512 + it * 256 + tid;  // 0..65535 float2 slots
            int c = o >> 9;                             // 512 float2 per column
            int r = (o & 511) << 1;
            int j = c >> 2;
            int b = c & 3;
            int t = j * LCH + s - (HW - 1);
            float2 v;
            if (t < 1) {
                v = __ldcg(reinterpret_cast<const float2*>(&g_Y[p][c][r]));
            } else {
                int rb2 = r >> 7, rl = r & 127;
                float sx = 0.f, sy = 0.f;
                #pragma unroll
                for (int q = 0; q < NKS; ++q) {
                    float2 pv = __ldcg(reinterpret_cast<const float2*>(&g_P[rb2][q][c][rl]));
                    sx += pv.x; sy += pv.y;
                }
                int idx = b * SEQ + (t - 1);
                long long id = ids64 ? (long long)ids32[2 * idx] : (long long)ids32[idx];
                float2 e = *reinterpret_cast<const float2*>(&emb[(size_t)id * D + r]);
                v = make_float2(sx + e.x, sy + e.y);
            }
            __stcg(reinterpret_cast<float2*>(&g_Y[p ^ 1][c][r]), v);
            if (s >= HW)
                *reinterpret_cast<float2*>(&out[((size_t)b * OUTSEQ + t) * D + r]) = v;
        }
        grid_barrier(++gen);
        p ^= 1;
    }
}

// ---------------------------------------------------------------------------
extern "C" void kernel_launch(void* const* d_in, const int* in_sizes, int n_in,
                              void* d_out, int out_size) {
    const int*   ids = (const int*)d_in[0];
    const float* emb = (const float*)d_in[1];
    const float* Mw  = (const float*)d_in[2];
    float*       out = (float*)d_out;

    (void)in_sizes; (void)n_in; (void)out_size;

    const int smem = (RT * KT + NCOL * KT) * (int)sizeof(float);  // 64KB
    cudaFuncSetAttribute(scan_kernel, cudaFuncAttributeMaxDynamicSharedMemorySize, smem);

    detect_kernel<<<1, 256>>>((const unsigned*)d_in[0]);
    init_kernel<<<(NCOL * D + THREADS - 1) / THREADS, THREADS>>>(emb, out);
    scan_kernel<<<GRID_MAIN, THREADS, smem>>>(ids, emb, Mw, out);
}

// round 7
// speedup vs baseline: 1.9174x; 1.0521x over previous
#include <cuda_runtime.h>
#include <cstdint>

// Problem constants
#define D        1024
#define NB       4
#define SEQ      2048
#define OUTSEQ   2049

// Chunked-scan parameters
#define CHUNKS   32
#define LCH      64           // SEQ / CHUNKS
#define HW       48           // warm-up; 0.64^48 ~ 2e-10
#define SSTEPS   (LCH + HW)   // 112 GEMM steps (+1 stage-only epilogue iter)
#define NCOL     (CHUNKS*NB)  // 128 state columns

// GEMM tiling: Ynew(1024 x 128) += M(1024x1024) * Y(1024x128) per step
#define NRB      8            // row blocks of RT=128
#define RT       128
#define NKS      16           // K splits of KT=64
#define KT       64
#define GRID_MAIN (NRB*NKS)   // 128 CTAs
#define THREADS  256

// Device state: triple-buffered accumulators.
// step s: stage-read buf[s%3], REDG into buf[(s+1)%3], x-inject buf[(s+2)%3]
__device__ float    g_Y[3][NCOL][D];
__device__ unsigned g_barCount;
__device__ unsigned g_barGen;
__device__ int      g_ids64;

// packed fp32x2 FMA (Blackwell, PTX-only)
__device__ __forceinline__ void fma2(float2& d, const float2& a, const float2& b) {
    asm("fma.rn.f32x2 %0, %1, %2, %0;"
        : "+l"(*reinterpret_cast<unsigned long long*>(&d))
        : "l"(*reinterpret_cast<const unsigned long long*>(&a)),
          "l"(*reinterpret_cast<const unsigned long long*>(&b)));
}

// L2 vector reduction (no return) — sm_90+ vectorized red
__device__ __forceinline__ void redg_add4(float* p, float4 v) {
    asm volatile("red.global.add.v4.f32 [%0], {%1, %2, %3, %4};"
                 :: "l"(p), "f"(v.x), "f"(v.y), "f"(v.z), "f"(v.w) : "memory");
}

// gpu-scope release/acquire primitives (no membar, no L1 flush)
__device__ __forceinline__ unsigned atom_add_release(unsigned* p, unsigned v) {
    unsigned old;
    asm volatile("atom.release.gpu.global.add.u32 %0, [%1], %2;"
                 : "=r"(old) : "l"(p), "r"(v) : "memory");
    return old;
}
__device__ __forceinline__ unsigned ld_acquire(unsigned* p) {
    unsigned v;
    asm volatile("ld.acquire.gpu.global.u32 %0, [%1];" : "=r"(v) : "l"(p) : "memory");
    return v;
}
__device__ __forceinline__ void st_release(unsigned* p, unsigned v) {
    asm volatile("st.release.gpu.global.u32 [%0], %1;" :: "l"(p), "r"(v) : "memory");
}
__device__ __forceinline__ void st_relaxed(unsigned* p, unsigned v) {
    asm volatile("st.relaxed.gpu.global.u32 [%0], %1;" :: "l"(p), "r"(v) : "memory");
}

__device__ __forceinline__ void grid_barrier(unsigned gen) {
    __syncthreads();
    if (threadIdx.x == 0) {
        unsigned arrived = atom_add_release(&g_barCount, 1u);
        if (arrived == GRID_MAIN - 1) {
            st_relaxed(&g_barCount, 0u);
            st_release(&g_barGen, gen);
        } else {
            while (ld_acquire(&g_barGen) < gen) { __nanosleep(32); }
        }
    }
    __syncthreads();
}

// ---------------------------------------------------------------------------
__global__ void detect_kernel(const unsigned* ids32) {
    __shared__ unsigned red[256];
    unsigned acc = 0;
    for (int i = threadIdx.x; i < NB * SEQ; i += 256)
        acc |= ids32[2 * i + 1];
    red[threadIdx.x] = acc;
    __syncthreads();
    for (int off = 128; off > 0; off >>= 1) {
        if (threadIdx.x < off) red[threadIdx.x] |= red[threadIdx.x + off];
        __syncthreads();
    }
    if (threadIdx.x == 0) g_ids64 = (red[0] == 0u) ? 1 : 0;
}

// ---------------------------------------------------------------------------
// Init: buf0 = 0 (initial states), buf1 = x(step 0), out[b][0] = emb[0],
// barrier vars. One thread per float4 of a buffer (32768 threads).
// ---------------------------------------------------------------------------
__global__ void init_kernel(const int* __restrict__ ids32,
                            const float* __restrict__ emb,
                            float* __restrict__ out) {
    int i = blockIdx.x * blockDim.x + threadIdx.x;   // 0..32767
    if (i == 0) { g_barCount = 0u; g_barGen = 0u; }
    const int ids64 = g_ids64;

    int c  = i >> 8;            // column 0..127
    int rq = (i & 255) << 2;    // row quad

    *reinterpret_cast<float4*>(&g_Y[0][c][rq]) = make_float4(0.f, 0.f, 0.f, 0.f);

    // buf1 = x injected by step 0: state time t = j*LCH - (HW-1)
    int j = c >> 2, b = c & 3;
    int t = j * LCH - (HW - 1);
    float4 xv = make_float4(0.f, 0.f, 0.f, 0.f);
    if (t >= 1) {
        int idx = b * SEQ + t - 1;
        long long id = ids64 ? (long long)ids32[2 * idx] : (long long)ids32[idx];
        xv = *reinterpret_cast<const float4*>(&emb[(size_t)id * D + rq]);
    } else if (t == 0) {
        xv = *reinterpret_cast<const float4*>(&emb[rq]);   // padded token 0
    }
    *reinterpret_cast<float4*>(&g_Y[1][c][rq]) = xv;

    if (i < NB * 256) {
        int b2 = i >> 8;
        int r4 = (i & 255) << 2;
        *reinterpret_cast<float4*>(&out[(size_t)b2 * OUTSEQ * D + r4]) =
            *reinterpret_cast<const float4*>(&emb[r4]);
    }
}

// ---------------------------------------------------------------------------
// Main persistent kernel. ONE grid barrier per step.
// smem (float2 view): Ms2[128 r][32 kp] swizzled, persistent (32KB)
//                     Ys2[128 c][32 kp] swizzled, restaged per step (32KB)
// Swizzle: slot = row*32 + (kp ^ (row>>3))
// ---------------------------------------------------------------------------
__global__ void __launch_bounds__(THREADS, 1)
scan_kernel(const int* __restrict__ ids32,
            const float* __restrict__ emb,
            const float* __restrict__ Mw,
            float* __restrict__ out) {
    extern __shared__ float sm[];
    float2* Ms2 = reinterpret_cast<float2*>(sm);             // 128*32 float2
    float2* Ys2 = reinterpret_cast<float2*>(sm + RT * KT);   // 128*32 float2

    const int tid = threadIdx.x;
    const int rb  = blockIdx.x >> 4;          // 8 row blocks
    const int ks  = blockIdx.x & (NKS - 1);   // 16 K splits
    const int r0c = rb * RT;
    const int k0  = ks * KT;
    const int ids64 = g_ids64;

    // Load M slice once, swizzled
    for (int i = tid; i < RT * KT / 2; i += THREADS) {
        int r  = i >> 5;
        int kp = i & 31;
        float2 v = *reinterpret_cast<const float2*>(&Mw[(size_t)(r0c + r) * D + k0 + 2 * kp]);
        Ms2[r * 32 + (kp ^ (r >> 3))] = v;
    }

    const int rowg = tid & 15;     // 16 row groups of 8 rows
    const int colg = tid >> 4;     // 16 col groups of 8 cols
    const int r0 = rowg * 8;
    const int c0 = colg * 8;
    const float2* __restrict__ msp = Ms2 + r0 * 32;
    const float2* __restrict__ ysp = Ys2 + c0 * 32;

    unsigned gen = 0;
    for (int s = 0; s <= SSTEPS; ++s) {
        // ---- Stage current state buf[s%3] into smem; fold in output writes
        const float* __restrict__ Yb = &g_Y[s % 3][0][0];
        const bool wout = (s > HW);
        for (int i = tid; i < NCOL * (KT / 4); i += THREADS) {   // 2048 -> 8/thread
            int c  = i >> 4;
            int kq = (i & 15) << 2;
            float4 v = __ldcg(reinterpret_cast<const float4*>(Yb + c * D + k0 + kq));
            int sw  = c >> 3;
            int kp0 = kq >> 1;
            Ys2[c * 32 + (kp0 ^ sw)]       = make_float2(v.x, v.y);
            Ys2[c * 32 + ((kp0 + 1) ^ sw)] = make_float2(v.z, v.w);
            if (wout && ((c & 7) == rb)) {
                int t = (c >> 2) * LCH + s - HW;      // state time; 1..(j+1)*LCH
                *reinterpret_cast<float4*>(
                    &out[((size_t)(c & 3) * OUTSEQ + t) * D + k0 + kq]) = v;
            }
        }
        if (s == SSTEPS) break;   // epilogue iteration: outputs only
        __syncthreads();

        // ---- 8x8 register-tile GEMM, K-pair-packed f32x2
        float2 acc[8][8];
        #pragma unroll
        for (int i = 0; i < 8; ++i)
            #pragma unroll
            for (int j = 0; j < 8; ++j) acc[i][j] = make_float2(0.f, 0.f);

        #pragma unroll 4
        for (int kp = 0; kp < 32; ++kp) {
            int sa = kp ^ rowg;
            int sb = kp ^ colg;
            float2 a[8], b[8];
            #pragma unroll
            for (int i = 0; i < 8; ++i) a[i] = msp[i * 32 + sa];
            #pragma unroll
            for (int j = 0; j < 8; ++j) b[j] = ysp[j * 32 + sb];
            #pragma unroll
            for (int i = 0; i < 8; ++i)
                #pragma unroll
                for (int j = 0; j < 8; ++j) fma2(acc[i][j], a[i], b[j]);
        }

        // ---- Accumulate partial tile into next state via L2 reductions
        {
            float* Yn = &g_Y[(s + 1) % 3][0][0];
            #pragma unroll
            for (int j = 0; j < 8; ++j) {
                float4 v0 = make_float4(acc[0][j].x + acc[0][j].y, acc[1][j].x + acc[1][j].y,
                                        acc[2][j].x + acc[2][j].y, acc[3][j].x + acc[3][j].y);
                float4 v1 = make_float4(acc[4][j].x + acc[4][j].y, acc[5][j].x + acc[5][j].y,
                                        acc[6][j].x + acc[6][j].y, acc[7][j].x + acc[7][j].y);
                float* base = Yn + (size_t)(c0 + j) * D + r0c + r0;
                redg_add4(base,     v0);
                redg_add4(base + 4, v1);
            }
        }

        // ---- Inject x into the buffer two steps ahead (replaces zeroing)
        if (s < SSTEPS - 1) {
            float* Yi = &g_Y[(s + 2) % 3][0][0];
            int o  = blockIdx.x * THREADS + tid;   // 0..32767, one float4 each
            int c  = o >> 8;
            int rq = (o & 255) << 2;
            int j = c >> 2, b = c & 3;
            int t = j * LCH + s + 2 - HW;          // time of state made at step s+1
            float4 xv = make_float4(0.f, 0.f, 0.f, 0.f);
            if (t >= 0 && t <= SEQ) {
                long long id = 0;
                if (t >= 1) {
                    int idx = b * SEQ + t - 1;
                    id = ids64 ? (long long)ids32[2 * idx] : (long long)ids32[idx];
                }
                xv = *reinterpret_cast<const float4*>(&emb[(size_t)id * D + rq]);
            }
            __stcg(reinterpret_cast<float4*>(Yi + (size_t)c * D + rq), xv);
        }

        grid_barrier(++gen);
    }
}

// ---------------------------------------------------------------------------
extern "C" void kernel_launch(void* const* d_in, const int* in_sizes, int n_in,
                              void* d_out, int out_size) {
    const int*   ids = (const int*)d_in[0];
    const float* emb = (const float*)d_in[1];
    const float* Mw  = (const float*)d_in[2];
    float*       out = (float*)d_out;

    (void)in_sizes; (void)n_in; (void)out_size;

    const int smem = (RT * KT + NCOL * KT) * (int)sizeof(float);  // 64KB
    cudaFuncSetAttribute(scan_kernel, cudaFuncAttributeMaxDynamicSharedMemorySize, smem);

    detect_kernel<<<1, 256>>>((const unsigned*)d_in[0]);
    init_kernel<<<128, THREADS>>>(ids, emb, out);
    scan_kernel<<<GRID_MAIN, THREADS, smem>>>(ids, emb, Mw, out);
}

// round 9
// speedup vs baseline: 2.6958x; 1.4060x over previous
#include <cuda_runtime.h>
#include <cuda_bf16.h>
#include <cstdint>

// Problem constants
#define D        1024
#define NB       4
#define SEQ      2048
#define OUTSEQ   2049

// Chunked-scan parameters
#define CHUNKS   32
#define LCH      64            // SEQ / CHUNKS
#define HW       48            // warm-up; 0.64^48 ~ 2e-10
#define SSTEPS   (LCH + HW)    // 112
#define NCOL     (CHUNKS*NB)   // 128 state columns

// GEMM grid: Ynew(1024 x 128) = M(1024x1024) * Y(1024x128) per step
#define NRB      8             // row blocks of RT=128
#define RT       128
#define NKS      16            // K splits of KT=64
#define KT       64
#define GRID_MAIN (NRB*NKS)    // 128 CTAs
#define THREADS  256

// smem: Bh/Bl tiles: 128 cols x 64 k bf16 = 16KB each, SW128 swizzled
#define BTILE    16384
#define SMEM_REQ (2*BTILE + 1024)

#define SW(o) ((unsigned)(o) ^ ((((unsigned)(o)) >> 3) & 0x70))

// Device state
__device__ float    g_Y[2][NCOL][D];            // double-buffered chain states
__device__ float    g_P[NRB][NKS][NCOL][RT];    // K-split partials [c][r]
__device__ unsigned g_barCount;
__device__ unsigned g_barGen;

// ---------------------------------------------------------------------------
// PTX helpers (all baseline sm_103 — no 'a' features)
// ---------------------------------------------------------------------------
__device__ __forceinline__ unsigned smem_u32(const void* p) {
    unsigned a;
    asm("{ .reg .u64 t; cvta.to.shared.u64 t, %1; cvt.u32.u64 %0, t; }"
        : "=r"(a) : "l"(p));
    return a;
}
__device__ __forceinline__ void mma_bf16(float* d, const unsigned* a,
                                         unsigned b0, unsigned b1) {
    asm volatile("mma.sync.aligned.m16n8k16.row.col.f32.bf16.bf16.f32 "
                 "{%0,%1,%2,%3}, {%4,%5,%6,%7}, {%8,%9}, {%0,%1,%2,%3};"
                 : "+f"(d[0]), "+f"(d[1]), "+f"(d[2]), "+f"(d[3])
                 : "r"(a[0]), "r"(a[1]), "r"(a[2]), "r"(a[3]), "r"(b0), "r"(b1));
}
__device__ __forceinline__ void ldsm_x2(unsigned& r0, unsigned& r1, unsigned addr) {
    asm volatile("ldmatrix.sync.aligned.m8n8.x2.shared.b16 {%0,%1}, [%2];"
                 : "=r"(r0), "=r"(r1) : "r"(addr));
}

// gpu-scope release/acquire barrier primitives
__device__ __forceinline__ unsigned atom_add_release(unsigned* p, unsigned v) {
    unsigned old;
    asm volatile("atom.release.gpu.global.add.u32 %0, [%1], %2;"
                 : "=r"(old) : "l"(p), "r"(v) : "memory");
    return old;
}
__device__ __forceinline__ unsigned ld_acquire(unsigned* p) {
    unsigned v;
    asm volatile("ld.acquire.gpu.global.u32 %0, [%1];" : "=r"(v) : "l"(p) : "memory");
    return v;
}
__device__ __forceinline__ void st_release(unsigned* p, unsigned v) {
    asm volatile("st.release.gpu.global.u32 [%0], %1;" :: "l"(p), "r"(v) : "memory");
}
__device__ __forceinline__ void st_relaxed(unsigned* p, unsigned v) {
    asm volatile("st.relaxed.gpu.global.u32 [%0], %1;" :: "l"(p), "r"(v) : "memory");
}
__device__ __forceinline__ void grid_barrier(unsigned gen) {
    __syncthreads();
    if (threadIdx.x == 0) {
        unsigned arrived = atom_add_release(&g_barCount, 1u);
        if (arrived == GRID_MAIN - 1) {
            st_relaxed(&g_barCount, 0u);
            st_release(&g_barGen, gen);
        } else {
            while (ld_acquire(&g_barGen) < gen) { __nanosleep(32); }
        }
    }
    __syncthreads();
}

__device__ __forceinline__ unsigned pack_hi(float x, float y,
                                            float& rx, float& ry) {
    __nv_bfloat162 h;
    h.x = __float2bfloat16(x);
    h.y = __float2bfloat16(y);
    rx = x - __bfloat162float(h.x);
    ry = y - __bfloat162float(h.y);
    return *reinterpret_cast<unsigned*>(&h);
}
__device__ __forceinline__ unsigned pack_bf2(float x, float y) {
    __nv_bfloat162 h;
    h.x = __float2bfloat16(x);
    h.y = __float2bfloat16(y);
    return *reinterpret_cast<unsigned*>(&h);
}

// ---------------------------------------------------------------------------
// Reset barrier vars before each (re)play of the persistent kernel
// ---------------------------------------------------------------------------
__global__ void reset_kernel() {
    g_barCount = 0u;
    g_barGen   = 0u;
}

// ---------------------------------------------------------------------------
// Fused persistent kernel
// ---------------------------------------------------------------------------
__global__ void __launch_bounds__(THREADS, 1)
scan_kernel(const unsigned* __restrict__ ids_u,
            const float* __restrict__ emb,
            const float* __restrict__ Mw,
            float* __restrict__ out) {
    extern __shared__ char smraw[];
    // round dynamic smem base up to 1024B so SW128 swizzle is bank-exact
    unsigned sb0 = smem_u32(smraw);
    unsigned pad = (1024u - (sb0 & 1023u)) & 1023u;
    char* smem = smraw + pad;
    const unsigned sbh = sb0 + pad;           // Bh tile (shared-space addr)
    const unsigned sbl = sbh + BTILE;         // Bl tile

    const int tid = threadIdx.x;
    const int wid = tid >> 5;
    const int lid = tid & 31;
    const int rb  = blockIdx.x >> 4;          // 8 row blocks
    const int ks  = blockIdx.x & (NKS - 1);   // 16 K splits
    const int r0c = rb * RT;
    const int k0  = ks * KT;

    // ---- ids dtype detect (per-CTA, deterministic): int64 iff all odd words 0
    __shared__ unsigned sdet[8];
    {
        unsigned acc = 0;
        for (int i = tid; i < NB * SEQ; i += THREADS) acc |= ids_u[2 * i + 1];
        #pragma unroll
        for (int off = 16; off > 0; off >>= 1)
            acc |= __shfl_xor_sync(0xFFFFFFFFu, acc, off);
        if (lid == 0) sdet[wid] = acc;
    }

    // ---- A fragments (M slice, 16 rows per warp) -> registers, bf16 hi/lo
    // m16n8k16 A-frag: a0:(gr,kq) a1:(gr+8,kq) a2:(gr,kq+8) a3:(gr+8,kq+8)
    unsigned Ah[4][4], Al[4][4];
    {
        const int gr = lid >> 2;
        const int kq = (lid & 3) * 2;
        const int ra = r0c + wid * 16 + gr;
        #pragma unroll
        for (int kc = 0; kc < 4; ++kc) {
            const int kb = k0 + kc * 16 + kq;
            float2 f0 = *reinterpret_cast<const float2*>(&Mw[(size_t)ra * D + kb]);
            float2 f1 = *reinterpret_cast<const float2*>(&Mw[(size_t)(ra + 8) * D + kb]);
            float2 f2 = *reinterpret_cast<const float2*>(&Mw[(size_t)ra * D + kb + 8]);
            float2 f3 = *reinterpret_cast<const float2*>(&Mw[(size_t)(ra + 8) * D + kb + 8]);
            float lx, ly;
            Ah[kc][0] = pack_hi(f0.x, f0.y, lx, ly); Al[kc][0] = pack_bf2(lx, ly);
            Ah[kc][1] = pack_hi(f1.x, f1.y, lx, ly); Al[kc][1] = pack_bf2(lx, ly);
            Ah[kc][2] = pack_hi(f2.x, f2.y, lx, ly); Al[kc][2] = pack_bf2(lx, ly);
            Ah[kc][3] = pack_hi(f3.x, f3.y, lx, ly); Al[kc][3] = pack_bf2(lx, ly);
        }
    }

    // ---- init g_Y[0] (chain 0 = emb[0], rest 0) and out[:, 0, :]
    {
        int i0 = blockIdx.x * THREADS + tid;      // 0..32767, one float4 each
        int c  = i0 >> 8;
        int rq = (i0 & 255) << 2;
        float4 z = make_float4(0.f, 0.f, 0.f, 0.f);
        if (c < NB) z = *reinterpret_cast<const float4*>(&emb[rq]);
        __stcg(reinterpret_cast<float4*>(&g_Y[0][c][rq]), z);
        if (blockIdx.x < NB) {
            int r4 = tid << 2;
            *reinterpret_cast<float4*>(&out[(size_t)blockIdx.x * OUTSEQ * D + r4]) =
                *reinterpret_cast<const float4*>(&emb[r4]);
        }
    }
    __syncthreads();
    const int ids64 = ((sdet[0]|sdet[1]|sdet[2]|sdet[3]|sdet[4]|sdet[5]|sdet[6]|sdet[7]) == 0u) ? 1 : 0;
    const int* __restrict__ ids32 = reinterpret_cast<const int*>(ids_u);

    unsigned gen = 0;
    grid_barrier(++gen);

    int p = 0;
    for (int s = 0; s < SSTEPS; ++s) {
        // ---- Stage: Y slice (L2 loads) -> bf16 hi/lo, SW128-swizzled smem
        const float* __restrict__ Yb = &g_Y[p][0][0];
        for (int i = tid; i < NCOL * (KT / 4); i += THREADS) {   // 2048 -> 8/thread
            int c  = i >> 4;
            int kq = (i & 15) << 2;
            float4 v = __ldcg(reinterpret_cast<const float4*>(Yb + (size_t)c * D + k0 + kq));
            float l0, l1, l2, l3;
            unsigned h01 = pack_hi(v.x, v.y, l0, l1);
            unsigned h23 = pack_hi(v.z, v.w, l2, l3);
            unsigned l01 = pack_bf2(l0, l1);
            unsigned l23 = pack_bf2(l2, l3);
            unsigned off = SW(c * 128 + kq * 2);   // 8B-aligned within 16B unit
            *reinterpret_cast<unsigned long long*>(smem + off) =
                (unsigned long long)h01 | ((unsigned long long)h23 << 32);
            *reinterpret_cast<unsigned long long*>(smem + BTILE + off) =
                (unsigned long long)l01 | ((unsigned long long)l23 << 32);
        }
        __syncthreads();

        // ---- GEMM: D[16 x 128] per warp = A(16xKT) * Y(128xKT)^T, bf16x3
        float d[16][4];
        #pragma unroll
        for (int nt = 0; nt < 16; ++nt) {
            d[nt][0] = 0.f; d[nt][1] = 0.f; d[nt][2] = 0.f; d[nt][3] = 0.f;
        }

        const unsigned lrow = (unsigned)((lid & 7) * 128 + ((lid & 8) ? 16 : 0));
        #pragma unroll
        for (int kc = 0; kc < 4; ++kc) {
            unsigned b0[16], b1[16];
            const unsigned koff = kc * 32;
            // Bh fragments for all 16 n-tiles
            #pragma unroll
            for (int nt = 0; nt < 16; ++nt)
                ldsm_x2(b0[nt], b1[nt], sbh + SW(nt * 1024 + lrow + koff));
            #pragma unroll
            for (int nt = 0; nt < 16; ++nt) {
                mma_bf16(d[nt], Ah[kc], b0[nt], b1[nt]);
                mma_bf16(d[nt], Al[kc], b0[nt], b1[nt]);
            }
            // Bl fragments (reuse regs)
            #pragma unroll
            for (int nt = 0; nt < 16; ++nt)
                ldsm_x2(b0[nt], b1[nt], sbl + SW(nt * 1024 + lrow + koff));
            #pragma unroll
            for (int nt = 0; nt < 16; ++nt)
                mma_bf16(d[nt], Ah[kc], b0[nt], b1[nt]);
        }

        // ---- Partial store: g_P[rb][ks][c][r] via L2
        {
            float* pb = &g_P[rb][ks][0][0];
            const int n0 = (lid & 3) * 2;
            const int rl = wid * 16 + (lid >> 2);
            #pragma unroll
            for (int nt = 0; nt < 16; ++nt) {
                const int cb = nt * 8 + n0;
                __stcg(&pb[(size_t)cb * RT + rl],           d[nt][0]);
                __stcg(&pb[(size_t)(cb + 1) * RT + rl],     d[nt][1]);
                __stcg(&pb[(size_t)cb * RT + rl + 8],       d[nt][2]);
                __stcg(&pb[(size_t)(cb + 1) * RT + rl + 8], d[nt][3]);
            }
        }
        grid_barrier(++gen);

        // ---- Phase B: reduce 16 K-splits + emb, advance state, write out
        #pragma unroll
        for (int it = 0; it < 2; ++it) {
            int o = blockIdx.x * 512 + it * 256 + tid;  // 0..65535 float2 slots
            int c = o >> 9;
            int r = (o & 511) << 1;
            int j = c >> 2;
            int b = c & 3;
            int t = j * LCH + s - (HW - 1);
            float2 v;
            if (t < 1) {
                v = __ldcg(reinterpret_cast<const float2*>(&g_Y[p][c][r]));
            } else {
                int rb2 = r >> 7, rl = r & 127;
                float sx = 0.f, sy = 0.f;
                #pragma unroll
                for (int q = 0; q < NKS; ++q) {
                    float2 pv = __ldcg(reinterpret_cast<const float2*>(&g_P[rb2][q][c][rl]));
                    sx += pv.x; sy += pv.y;
                }
                int idx = b * SEQ + (t - 1);
                long long id = ids64 ? (long long)ids32[2 * idx] : (long long)ids32[idx];
                float2 e = *reinterpret_cast<const float2*>(&emb[(size_t)id * D + r]);
                v = make_float2(sx + e.x, sy + e.y);
            }
            __stcg(reinterpret_cast<float2*>(&g_Y[p ^ 1][c][r]), v);
            if (s >= HW)
                *reinterpret_cast<float2*>(&out[((size_t)b * OUTSEQ + t) * D + r]) = v;
        }
        grid_barrier(++gen);
        p ^= 1;
    }
}

// ---------------------------------------------------------------------------
extern "C" void kernel_launch(void* const* d_in, const int* in_sizes, int n_in,
                              void* d_out, int out_size) {
    const unsigned* ids = (const unsigned*)d_in[0];
    const float*    emb = (const float*)d_in[1];
    const float*    Mw  = (const float*)d_in[2];
    float*          out = (float*)d_out;

    (void)in_sizes; (void)n_in; (void)out_size;

    cudaFuncSetAttribute(scan_kernel, cudaFuncAttributeMaxDynamicSharedMemorySize, SMEM_REQ);

    reset_kernel<<<1, 1>>>();
    scan_kernel<<<GRID_MAIN, THREADS, SMEM_REQ>>>(ids, emb, Mw, out);
}

// round 13
// speedup vs baseline: 2.8527x; 1.0582x over previous
#include <cuda_runtime.h>
#include <cuda_bf16.h>
#include <cstdint>

// Problem constants
#define D        1024
#define NB       4
#define SEQ      2048
#define OUTSEQ   2049

// Chunked-scan parameters
#define CHUNKS   32
#define LCH      64            // SEQ / CHUNKS
#define HW       48            // warm-up; 0.64^48 ~ 2e-10
#define SSTEPS   (LCH + HW)    // 112
#define NCOL     (CHUNKS*NB)   // 128 state columns

// GEMM grid: Ynew(1024 x 128) = M(1024x1024) * Y(1024x128) per step
#define NRB      8             // row blocks of RT=128
#define RT       128
#define NKS      16            // K splits of KT=64
#define KT       64
#define GRID_MAIN (NRB*NKS)    // 128 CTAs
#define THREADS  512           // 16 warps -> 4 per SMSP

// smem: Bh/Bl tiles: 128 cols x 64 k bf16 = 16KB each, SW128 swizzled
#define BTILE    16384
#define SMEM_REQ (2*BTILE + 1024)

#define SW(o) ((unsigned)(o) ^ ((((unsigned)(o)) >> 3) & 0x70))

// Device state
__device__ float    g_Y[2][NCOL][D];            // double-buffered chain states
__device__ float    g_P[NRB][NKS][NCOL][RT];    // K-split partials [c][r]
__device__ unsigned g_barCount;
__device__ unsigned g_barGen;

// ---------------------------------------------------------------------------
// PTX helpers (baseline sm_103 only)
// ---------------------------------------------------------------------------
__device__ __forceinline__ unsigned smem_u32(const void* p) {
    unsigned a;
    asm("{ .reg .u64 t; cvta.to.shared.u64 t, %1; cvt.u32.u64 %0, t; }"
        : "=r"(a) : "l"(p));
    return a;
}
__device__ __forceinline__ void mma_bf16(float* d, const unsigned* a,
                                         unsigned b0, unsigned b1) {
    asm volatile("mma.sync.aligned.m16n8k16.row.col.f32.bf16.bf16.f32 "
                 "{%0,%1,%2,%3}, {%4,%5,%6,%7}, {%8,%9}, {%0,%1,%2,%3};"
                 : "+f"(d[0]), "+f"(d[1]), "+f"(d[2]), "+f"(d[3])
                 : "r"(a[0]), "r"(a[1]), "r"(a[2]), "r"(a[3]), "r"(b0), "r"(b1));
}
__device__ __forceinline__ void ldsm_x2(unsigned& r0, unsigned& r1, unsigned addr) {
    asm volatile("ldmatrix.sync.aligned.m8n8.x2.shared.b16 {%0,%1}, [%2];"
                 : "=r"(r0), "=r"(r1) : "r"(addr));
}

// gpu-scope release/acquire barrier primitives
__device__ __forceinline__ unsigned atom_add_release(unsigned* p, unsigned v) {
    unsigned old;
    asm volatile("atom.release.gpu.global.add.u32 %0, [%1], %2;"
                 : "=r"(old) : "l"(p), "r"(v) : "memory");
    return old;
}
__device__ __forceinline__ unsigned ld_acquire(unsigned* p) {
    unsigned v;
    asm volatile("ld.acquire.gpu.global.u32 %0, [%1];" : "=r"(v) : "l"(p) : "memory");
    return v;
}
__device__ __forceinline__ void st_release(unsigned* p, unsigned v) {
    asm volatile("st.release.gpu.global.u32 [%0], %1;" :: "l"(p), "r"(v) : "memory");
}
__device__ __forceinline__ void st_relaxed(unsigned* p, unsigned v) {
    asm volatile("st.relaxed.gpu.global.u32 [%0], %1;" :: "l"(p), "r"(v) : "memory");
}
__device__ __forceinline__ void grid_barrier(unsigned gen) {
    __syncthreads();
    if (threadIdx.x == 0) {
        unsigned arrived = atom_add_release(&g_barCount, 1u);
        if (arrived == GRID_MAIN - 1) {
            st_relaxed(&g_barCount, 0u);
            st_release(&g_barGen, gen);
        } else {
            while (ld_acquire(&g_barGen) < gen) { __nanosleep(32); }
        }
    }
    __syncthreads();
}

__device__ __forceinline__ unsigned pack_hi(float x, float y,
                                            float& rx, float& ry) {
    __nv_bfloat162 h;
    h.x = __float2bfloat16(x);
    h.y = __float2bfloat16(y);
    rx = x - __bfloat162float(h.x);
    ry = y - __bfloat162float(h.y);
    return *reinterpret_cast<unsigned*>(&h);
}
__device__ __forceinline__ unsigned pack_bf2(float x, float y) {
    __nv_bfloat162 h;
    h.x = __float2bfloat16(x);
    h.y = __float2bfloat16(y);
    return *reinterpret_cast<unsigned*>(&h);
}

// ---------------------------------------------------------------------------
// Reset barrier vars before each (re)play of the persistent kernel
// ---------------------------------------------------------------------------
__global__ void reset_kernel() {
    g_barCount = 0u;
    g_barGen   = 0u;
}

// ---------------------------------------------------------------------------
// Fused persistent kernel (16 warps/CTA)
// ---------------------------------------------------------------------------
__global__ void __launch_bounds__(THREADS, 1)
scan_kernel(const unsigned* __restrict__ ids_u,
            const float* __restrict__ emb,
            const float* __restrict__ Mw,
            float* __restrict__ out) {
    extern __shared__ char smraw[];
    unsigned sb0 = smem_u32(smraw);
    unsigned pad = (1024u - (sb0 & 1023u)) & 1023u;
    char* smem = smraw + pad;
    const unsigned sbh = sb0 + pad;           // Bh tile
    const unsigned sbl = sbh + BTILE;         // Bl tile

    const int tid = threadIdx.x;
    const int wid = tid >> 5;                 // 0..15
    const int lid = tid & 31;
    const int rb  = blockIdx.x >> 4;          // 8 row blocks
    const int ks  = blockIdx.x & (NKS - 1);   // 16 K splits
    const int r0c = rb * RT;
    const int k0  = ks * KT;

    const int rowgrp = wid & 7;               // 8 row groups of 16 rows
    const int ch     = wid >> 3;              // col half: 0 -> cols 0-63, 1 -> 64-127

    // ---- ids dtype detect (per-CTA, deterministic): int64 iff all odd words 0
    __shared__ unsigned sdet[16];
    {
        unsigned acc = 0;
        for (int i = tid; i < NB * SEQ; i += THREADS) acc |= ids_u[2 * i + 1];
        #pragma unroll
        for (int off = 16; off > 0; off >>= 1)
            acc |= __shfl_xor_sync(0xFFFFFFFFu, acc, off);
        if (lid == 0) sdet[wid] = acc;
    }

    // ---- A fragments (16 rows per warp) -> registers, bf16 hi/lo
    unsigned Ah[4][4], Al[4][4];
    {
        const int gr = lid >> 2;
        const int kq = (lid & 3) * 2;
        const int ra = r0c + rowgrp * 16 + gr;
        #pragma unroll
        for (int kc = 0; kc < 4; ++kc) {
            const int kb = k0 + kc * 16 + kq;
            float2 f0 = *reinterpret_cast<const float2*>(&Mw[(size_t)ra * D + kb]);
            float2 f1 = *reinterpret_cast<const float2*>(&Mw[(size_t)(ra + 8) * D + kb]);
            float2 f2 = *reinterpret_cast<const float2*>(&Mw[(size_t)ra * D + kb + 8]);
            float2 f3 = *reinterpret_cast<const float2*>(&Mw[(size_t)(ra + 8) * D + kb + 8]);
            float lx, ly;
            Ah[kc][0] = pack_hi(f0.x, f0.y, lx, ly); Al[kc][0] = pack_bf2(lx, ly);
            Ah[kc][1] = pack_hi(f1.x, f1.y, lx, ly); Al[kc][1] = pack_bf2(lx, ly);
            Ah[kc][2] = pack_hi(f2.x, f2.y, lx, ly); Al[kc][2] = pack_bf2(lx, ly);
            Ah[kc][3] = pack_hi(f3.x, f3.y, lx, ly); Al[kc][3] = pack_bf2(lx, ly);
        }
    }

    // ---- init g_Y[0] (chain 0 = emb[0], rest 0) and out[:, 0, :]
    {
        int i0 = blockIdx.x * THREADS + tid;      // 0..65535
        if (i0 < NCOL * 256) {                    // one float4 each, 32768 total
            int c  = i0 >> 8;
            int rq = (i0 & 255) << 2;
            float4 z = make_float4(0.f, 0.f, 0.f, 0.f);
            if (c < NB) z = *reinterpret_cast<const float4*>(&emb[rq]);
            __stcg(reinterpret_cast<float4*>(&g_Y[0][c][rq]), z);
        }
        if (blockIdx.x < NB && tid < 256) {
            int r4 = tid << 2;
            *reinterpret_cast<float4*>(&out[(size_t)blockIdx.x * OUTSEQ * D + r4]) =
                *reinterpret_cast<const float4*>(&emb[r4]);
        }
    }
    __syncthreads();
    unsigned det = 0;
    #pragma unroll
    for (int i = 0; i < 16; ++i) det |= sdet[i];
    const int ids64 = (det == 0u) ? 1 : 0;
    const int* __restrict__ ids32 = reinterpret_cast<const int*>(ids_u);

    unsigned gen = 0;
    grid_barrier(++gen);

    int p = 0;
    for (int s = 0; s < SSTEPS; ++s) {
        // ---- Stage: Y slice (L2 loads) -> bf16 hi/lo, SW128-swizzled smem
        const float* __restrict__ Yb = &g_Y[p][0][0];
        for (int i = tid; i < NCOL * (KT / 4); i += THREADS) {   // 2048 -> 4/thread
            int c  = i >> 4;
            int kq = (i & 15) << 2;
            float4 v = __ldcg(reinterpret_cast<const float4*>(Yb + (size_t)c * D + k0 + kq));
            float l0, l1, l2, l3;
            unsigned h01 = pack_hi(v.x, v.y, l0, l1);
            unsigned h23 = pack_hi(v.z, v.w, l2, l3);
            unsigned l01 = pack_bf2(l0, l1);
            unsigned l23 = pack_bf2(l2, l3);
            unsigned off = SW(c * 128 + kq * 2);
            *reinterpret_cast<unsigned long long*>(smem + off) =
                (unsigned long long)h01 | ((unsigned long long)h23 << 32);
            *reinterpret_cast<unsigned long long*>(smem + BTILE + off) =
                (unsigned long long)l01 | ((unsigned long long)l23 << 32);
        }
        __syncthreads();

        // ---- GEMM: per warp D[16 x 64] = A(16xKT) * Yhalf(64xKT)^T, bf16x3
        float d[8][4];
        #pragma unroll
        for (int nt = 0; nt < 8; ++nt) {
            d[nt][0] = 0.f; d[nt][1] = 0.f; d[nt][2] = 0.f; d[nt][3] = 0.f;
        }

        const unsigned lrow  = (unsigned)((lid & 7) * 128 + ((lid & 8) ? 16 : 0));
        const unsigned ntoff = (unsigned)(ch * 8 * 1024);
        #pragma unroll
        for (int kc = 0; kc < 4; ++kc) {
            unsigned b0[8], b1[8];
            const unsigned koff = kc * 32;
            #pragma unroll
            for (int nt = 0; nt < 8; ++nt)
                ldsm_x2(b0[nt], b1[nt], sbh + SW(ntoff + nt * 1024 + lrow + koff));
            #pragma unroll
            for (int nt = 0; nt < 8; ++nt) {
                mma_bf16(d[nt], Ah[kc], b0[nt], b1[nt]);
                mma_bf16(d[nt], Al[kc], b0[nt], b1[nt]);
            }
            #pragma unroll
            for (int nt = 0; nt < 8; ++nt)
                ldsm_x2(b0[nt], b1[nt], sbl + SW(ntoff + nt * 1024 + lrow + koff));
            #pragma unroll
            for (int nt = 0; nt < 8; ++nt)
                mma_bf16(d[nt], Ah[kc], b0[nt], b1[nt]);
        }

        // ---- Partial store: g_P[rb][ks][c][r] via L2
        {
            float* pb = &g_P[rb][ks][0][0];
            const int n0 = (lid & 3) * 2;
            const int rl = rowgrp * 16 + (lid >> 2);
            #pragma unroll
            for (int nt = 0; nt < 8; ++nt) {
                const int cb = (ch * 8 + nt) * 8 + n0;
                __stcg(&pb[(size_t)cb * RT + rl],           d[nt][0]);
                __stcg(&pb[(size_t)(cb + 1) * RT + rl],     d[nt][1]);
                __stcg(&pb[(size_t)cb * RT + rl + 8],       d[nt][2]);
                __stcg(&pb[(size_t)(cb + 1) * RT + rl + 8], d[nt][3]);
            }
        }
        grid_barrier(++gen);

        // ---- Phase B: reduce 16 K-splits + emb, advance state, write out
        {
            int o = blockIdx.x * THREADS + tid;    // 0..65535 float2 slots, 1/thread
            int c = o >> 9;
            int r = (o & 511) << 1;
            int j = c >> 2;
            int b = c & 3;
            int t = j * LCH + s - (HW - 1);
            float2 v;
            if (t < 1) {
                v = __ldcg(reinterpret_cast<const float2*>(&g_Y[p][c][r]));
            } else {
                int rb2 = r >> 7, rl = r & 127;
                float sx = 0.f, sy = 0.f;
                #pragma unroll
                for (int q = 0; q < NKS; ++q) {
                    float2 pv = __ldcg(reinterpret_cast<const float2*>(&g_P[rb2][q][c][rl]));
                    sx += pv.x; sy += pv.y;
                }
                int idx = b * SEQ + (t - 1);
                long long id = ids64 ? (long long)ids32[2 * idx] : (long long)ids32[idx];
                float2 e = *reinterpret_cast<const float2*>(&emb[(size_t)id * D + r]);
                v = make_float2(sx + e.x, sy + e.y);
            }
            __stcg(reinterpret_cast<float2*>(&g_Y[p ^ 1][c][r]), v);
            if (s >= HW)
                *reinterpret_cast<float2*>(&out[((size_t)b * OUTSEQ + t) * D + r]) = v;
        }
        grid_barrier(++gen);
        p ^= 1;
    }
}

// ---------------------------------------------------------------------------
extern "C" void kernel_launch(void* const* d_in, const int* in_sizes, int n_in,
                              void* d_out, int out_size) {
    const unsigned* ids = (const unsigned*)d_in[0];
    const float*    emb = (const float*)d_in[1];
    const float*    Mw  = (const float*)d_in[2];
    float*          out = (float*)d_out;

    (void)in_sizes; (void)n_in; (void)out_size;

    cudaFuncSetAttribute(scan_kernel, cudaFuncAttributeMaxDynamicSharedMemorySize, SMEM_REQ);

    reset_kernel<<<1, 1>>>();
    scan_kernel<<<GRID_MAIN, THREADS, SMEM_REQ>>>(ids, emb, Mw, out);
}